// round 1
// baseline (speedup 1.0000x reference)
#include <cuda_runtime.h>

// ---------------------------------------------------------------------------
// LQActiv (2-bit learned quantization of activations), Q_T = 1.
//
// out[0..N)   = quantized activations wq (fp32)
// out[N..N+2) = new_basis = 0.9*basis + 0.1*v, v from 2x2 LS refit
//
// Fused single pass over x: quantize + write wq + accumulate
//   S  = sum(e0*e1)   (int)
//   b0 = sum(e0*w)    (fp32 per-thread -> fp64 across threads)
//   b1 = sum(e1*w)
// ---------------------------------------------------------------------------

struct Tab {
    float t0, t1, t2;          // midpoint thresholds (sorted)
    float L0, L1, L2, L3;      // sorted quantization levels
    float e00, e01, e02, e03;  // encoding column 0 per sorted level (+-1)
    float e10, e11, e12, e13;  // encoding column 1 per sorted level (+-1)
    int   c0, c1, c2, c3;      // e0*e1 per sorted level (+-1)
};

__device__ Tab    g_tab;
__device__ double g_db0;
__device__ double g_db1;
__device__ long long g_ds;

// ---------------------------------------------------------------------------
// Setup: build sorted level/encoding table from basis, zero accumulators.
// Runs as a single thread; graph-replay safe (re-zeros every launch).
// ---------------------------------------------------------------------------
__global__ void lq_setup_kernel(const float* __restrict__ basis) {
    g_db0 = 0.0;
    g_db1 = 0.0;
    g_ds  = 0;

    float b0 = basis[0];
    float b1 = basis[1];

    // ENCODINGS rows (col0, col1) for codes 0..3: (-1,-1),(-1,+1),(+1,-1),(+1,+1)
    float L[4], e0[4], e1[4];
    const float E0i[4] = {-1.f, -1.f, 1.f, 1.f};
    const float E1i[4] = {-1.f, 1.f, -1.f, 1.f};
#pragma unroll
    for (int i = 0; i < 4; i++) {
        e0[i] = E0i[i];
        e1[i] = E1i[i];
        L[i]  = E0i[i] * b0 + E1i[i] * b1;
    }

    // Stable 4-element sort network on (L, e0, e1), ascending by L.
#pragma unroll
    for (int pass = 0; pass < 1; pass++) {
        const int pa[5] = {0, 2, 0, 1, 1};
        const int pb[5] = {1, 3, 2, 3, 2};
#pragma unroll
        for (int s = 0; s < 5; s++) {
            int a = pa[s], b = pb[s];
            if (L[a] > L[b]) {
                float tL = L[a];  L[a]  = L[b];  L[b]  = tL;
                float t0 = e0[a]; e0[a] = e0[b]; e0[b] = t0;
                float t1 = e1[a]; e1[a] = e1[b]; e1[b] = t1;
            }
        }
    }

    Tab t;
    t.t0 = 0.5f * (L[0] + L[1]);
    t.t1 = 0.5f * (L[1] + L[2]);
    t.t2 = 0.5f * (L[2] + L[3]);
    t.L0 = L[0]; t.L1 = L[1]; t.L2 = L[2]; t.L3 = L[3];
    t.e00 = e0[0]; t.e01 = e0[1]; t.e02 = e0[2]; t.e03 = e0[3];
    t.e10 = e1[0]; t.e11 = e1[1]; t.e12 = e1[2]; t.e13 = e1[3];
    t.c0 = (e0[0] * e1[0] > 0.f) ? 1 : -1;
    t.c1 = (e0[1] * e1[1] > 0.f) ? 1 : -1;
    t.c2 = (e0[2] * e1[2] > 0.f) ? 1 : -1;
    t.c3 = (e0[3] * e1[3] > 0.f) ? 1 : -1;
    g_tab = t;
}

// ---------------------------------------------------------------------------
// Per-element quantize step: select chains only (no dynamic indexing).
// searchsorted(thres, w, 'left') == (w>t0)+(w>t1)+(w>t2)
// ---------------------------------------------------------------------------
__device__ __forceinline__ float lq_step(float w, const Tab& t,
                                         float& s0, float& s1, int& sc) {
    bool hi = w > t.t1;
    float tcmp = hi ? t.t2 : t.t0;
    bool h2 = w > tcmp;
    float qv, a, b;
    int c;
    if (hi) {
        qv = h2 ? t.L3  : t.L2;
        a  = h2 ? t.e03 : t.e02;
        b  = h2 ? t.e13 : t.e12;
        c  = h2 ? t.c3  : t.c2;
    } else {
        qv = h2 ? t.L1  : t.L0;
        a  = h2 ? t.e01 : t.e00;
        b  = h2 ? t.e11 : t.e10;
        c  = h2 ? t.c1  : t.c0;
    }
    s0 = fmaf(a, w, s0);   // a in {-1,+1} -> exact +-w
    s1 = fmaf(b, w, s1);
    sc += c;
    return qv;
}

// ---------------------------------------------------------------------------
// Main fused kernel: float4 streaming quantize + reductions.
// ---------------------------------------------------------------------------
__global__ void __launch_bounds__(256)
lq_main_kernel(const float4* __restrict__ x, float4* __restrict__ out, int n4) {
    const Tab t = g_tab;

    float s0 = 0.f, s1 = 0.f;
    int sc = 0;

    int stride = gridDim.x * blockDim.x;
    for (int i = blockIdx.x * blockDim.x + threadIdx.x; i < n4; i += stride) {
        float4 v = x[i];
        float4 q;
        q.x = lq_step(v.x, t, s0, s1, sc);
        q.y = lq_step(v.y, t, s0, s1, sc);
        q.z = lq_step(v.z, t, s0, s1, sc);
        q.w = lq_step(v.w, t, s0, s1, sc);
        out[i] = q;
    }

    // ---- block reduction: warp shuffle in fp64/int64, then shared, then atomics
    double d0 = (double)s0;
    double d1 = (double)s1;
    long long dc = (long long)sc;

#pragma unroll
    for (int o = 16; o > 0; o >>= 1) {
        d0 += __shfl_down_sync(0xFFFFFFFFu, d0, o);
        d1 += __shfl_down_sync(0xFFFFFFFFu, d1, o);
        dc += __shfl_down_sync(0xFFFFFFFFu, dc, o);
    }

    __shared__ double sh0[8];
    __shared__ double sh1[8];
    __shared__ long long shc[8];

    int lane = threadIdx.x & 31;
    int warp = threadIdx.x >> 5;
    if (lane == 0) {
        sh0[warp] = d0;
        sh1[warp] = d1;
        shc[warp] = dc;
    }
    __syncthreads();

    if (warp == 0) {
        d0 = (lane < 8) ? sh0[lane] : 0.0;
        d1 = (lane < 8) ? sh1[lane] : 0.0;
        dc = (lane < 8) ? shc[lane] : 0LL;
#pragma unroll
        for (int o = 4; o > 0; o >>= 1) {
            d0 += __shfl_down_sync(0xFFFFFFFFu, d0, o);
            d1 += __shfl_down_sync(0xFFFFFFFFu, d1, o);
            dc += __shfl_down_sync(0xFFFFFFFFu, dc, o);
        }
        if (lane == 0) {
            atomicAdd(&g_db0, d0);
            atomicAdd(&g_db1, d1);
            atomicAdd((unsigned long long*)&g_ds, (unsigned long long)dc);
        }
    }
}

// ---------------------------------------------------------------------------
// Finish: handle any scalar tail (n % 4), solve 2x2, write new_basis.
// ---------------------------------------------------------------------------
__global__ void lq_finish_kernel(const float* __restrict__ x,
                                 const float* __restrict__ basis,
                                 float* __restrict__ out, int n) {
    const Tab t = g_tab;

    double d0 = g_db0;
    double d1 = g_db1;
    long long ds = g_ds;

    int tail = n & 3;
    for (int i = n - tail; i < n; i++) {
        float s0 = 0.f, s1 = 0.f;
        int sc = 0;
        out[i] = lq_step(x[i], t, s0, s1, sc);
        d0 += (double)s0;
        d1 += (double)s1;
        ds += sc;
    }

    double N   = (double)n;
    double S   = (double)ds;
    double det = N * N - S * S;
    double v0  = (N * d0 - S * d1) / det;
    double v1  = (N * d1 - S * d0) / det;

    out[n]     = 0.9f * basis[0] + 0.1f * (float)v0;
    out[n + 1] = 0.9f * basis[1] + 0.1f * (float)v1;
}

// ---------------------------------------------------------------------------
// Launch
// ---------------------------------------------------------------------------
extern "C" void kernel_launch(void* const* d_in, const int* in_sizes, int n_in,
                              void* d_out, int out_size) {
    // Inputs per setup_inputs(): x (N elems), basis (2 elems). Be defensive
    // about ordering.
    int xi = 0, bi = 1;
    if (n_in >= 2 && in_sizes[0] == 2 && in_sizes[1] != 2) { xi = 1; bi = 0; }

    const float* x     = (const float*)d_in[xi];
    const float* basis = (const float*)d_in[bi];
    float* out         = (float*)d_out;

    int n  = in_sizes[xi];
    int n4 = n >> 2;

    lq_setup_kernel<<<1, 1>>>(basis);

    const int threads = 256;
    const int blocks  = 1184;  // ~8 blocks/SM, grid-stride
    lq_main_kernel<<<blocks, threads>>>((const float4*)x, (float4*)out, n4);

    lq_finish_kernel<<<1, 1>>>(x, basis, out, n);
}

// round 2
// speedup vs baseline: 1.2210x; 1.2210x over previous
#include <cuda_runtime.h>

// ---------------------------------------------------------------------------
// LQActiv (2-bit learned quantization), Q_T = 1 — single fused kernel.
//
// out[0..N)   = quantized activations wq (fp32)
// out[N..N+2) = new_basis = 0.9*basis + 0.1*v, v from 2x2 LS refit
//
// Every thread derives the sorted level/threshold table inline from basis
// (2 broadcast loads + ~20 ALU ops). Grid-stride float4 streaming pass with
// evict-first hints; block reductions -> global atomics; the LAST block
// (atomic ticket) handles the scalar tail, solves the 2x2 system, writes the
// basis outputs, and re-zeros the accumulators so graph replays see the same
// initial state (globals are zero at module load; every launch ends zero).
// ---------------------------------------------------------------------------

__device__ double             g_db0;
__device__ double             g_db1;
__device__ long long          g_ds;
__device__ unsigned int       g_count;

struct Tab {
    float t0, t1, t2;          // midpoint thresholds (sorted)
    float L0, L1, L2, L3;      // sorted quantization levels
    float e00, e01, e02, e03;  // encoding col 0 per sorted level (+-1)
    float e10, e11, e12, e13;  // encoding col 1 per sorted level (+-1)
    int   c0, c1, c2, c3;      // e0*e1 per sorted level (+-1)
};

// Build sorted table from basis values (stable ascending sort by level).
__device__ __forceinline__ Tab make_tab(float b0, float b1) {
    float L[4], e0[4], e1[4];
    const float E0i[4] = {-1.f, -1.f, 1.f, 1.f};
    const float E1i[4] = {-1.f, 1.f, -1.f, 1.f};
#pragma unroll
    for (int i = 0; i < 4; i++) {
        e0[i] = E0i[i];
        e1[i] = E1i[i];
        L[i]  = E0i[i] * b0 + E1i[i] * b1;
    }
    // Stable 5-comparator network, ascending by L.
    const int pa[5] = {0, 2, 0, 1, 1};
    const int pb[5] = {1, 3, 2, 3, 2};
#pragma unroll
    for (int s = 0; s < 5; s++) {
        int a = pa[s], b = pb[s];
        if (L[a] > L[b]) {
            float tL = L[a];  L[a]  = L[b];  L[b]  = tL;
            float t0 = e0[a]; e0[a] = e0[b]; e0[b] = t0;
            float t1 = e1[a]; e1[a] = e1[b]; e1[b] = t1;
        }
    }
    Tab t;
    t.t0 = 0.5f * (L[0] + L[1]);
    t.t1 = 0.5f * (L[1] + L[2]);
    t.t2 = 0.5f * (L[2] + L[3]);
    t.L0 = L[0]; t.L1 = L[1]; t.L2 = L[2]; t.L3 = L[3];
    t.e00 = e0[0]; t.e01 = e0[1]; t.e02 = e0[2]; t.e03 = e0[3];
    t.e10 = e1[0]; t.e11 = e1[1]; t.e12 = e1[2]; t.e13 = e1[3];
    t.c0 = (e0[0] * e1[0] > 0.f) ? 1 : -1;
    t.c1 = (e0[1] * e1[1] > 0.f) ? 1 : -1;
    t.c2 = (e0[2] * e1[2] > 0.f) ? 1 : -1;
    t.c3 = (e0[3] * e1[3] > 0.f) ? 1 : -1;
    return t;
}

// searchsorted(thres, w, 'left') == (w>t0)+(w>t1)+(w>t2); select chains only.
__device__ __forceinline__ float lq_step(float w, const Tab& t,
                                         float& s0, float& s1, int& sc) {
    bool hi = w > t.t1;
    float tcmp = hi ? t.t2 : t.t0;
    bool h2 = w > tcmp;
    float qv, a, b;
    int c;
    if (hi) {
        qv = h2 ? t.L3  : t.L2;
        a  = h2 ? t.e03 : t.e02;
        b  = h2 ? t.e13 : t.e12;
        c  = h2 ? t.c3  : t.c2;
    } else {
        qv = h2 ? t.L1  : t.L0;
        a  = h2 ? t.e01 : t.e00;
        b  = h2 ? t.e11 : t.e10;
        c  = h2 ? t.c1  : t.c0;
    }
    s0 = fmaf(a, w, s0);   // a in {-1,+1} -> exact +-w
    s1 = fmaf(b, w, s1);
    sc += c;
    return qv;
}

__device__ __forceinline__ float4 lq_step4(float4 v, const Tab& t,
                                           float& s0, float& s1, int& sc) {
    float4 q;
    q.x = lq_step(v.x, t, s0, s1, sc);
    q.y = lq_step(v.y, t, s0, s1, sc);
    q.z = lq_step(v.z, t, s0, s1, sc);
    q.w = lq_step(v.w, t, s0, s1, sc);
    return q;
}

__global__ void __launch_bounds__(256)
lq_fused_kernel(const float* __restrict__ x,
                const float* __restrict__ basis,
                float* __restrict__ out, int n) {
    const float b0 = __ldg(&basis[0]);
    const float b1 = __ldg(&basis[1]);
    const Tab t = make_tab(b0, b1);

    const float4* __restrict__ x4   = (const float4*)x;
    float4* __restrict__       out4 = (float4*)out;
    const int n4 = n >> 2;

    float s0 = 0.f, s1 = 0.f;
    int sc = 0;

    const int stride = gridDim.x * blockDim.x;
    int i = blockIdx.x * blockDim.x + threadIdx.x;

    // 2-way software-pipelined grid-stride loop, streaming (evict-first) hints.
    for (; i + stride < n4; i += 2 * stride) {
        float4 v0 = __ldcs(&x4[i]);
        float4 v1 = __ldcs(&x4[i + stride]);
        float4 q0 = lq_step4(v0, t, s0, s1, sc);
        float4 q1 = lq_step4(v1, t, s0, s1, sc);
        __stcs(&out4[i], q0);
        __stcs(&out4[i + stride], q1);
    }
    for (; i < n4; i += stride) {
        float4 v = __ldcs(&x4[i]);
        float4 q = lq_step4(v, t, s0, s1, sc);
        __stcs(&out4[i], q);
    }

    // ---- block reduction: warp shuffle in fp64/int64, then shared, then atomics
    double d0 = (double)s0;
    double d1 = (double)s1;
    long long dc = (long long)sc;

#pragma unroll
    for (int o = 16; o > 0; o >>= 1) {
        d0 += __shfl_down_sync(0xFFFFFFFFu, d0, o);
        d1 += __shfl_down_sync(0xFFFFFFFFu, d1, o);
        dc += __shfl_down_sync(0xFFFFFFFFu, dc, o);
    }

    __shared__ double    sh0[8];
    __shared__ double    sh1[8];
    __shared__ long long shc[8];
    __shared__ bool      is_last;

    int lane = threadIdx.x & 31;
    int warp = threadIdx.x >> 5;
    if (lane == 0) {
        sh0[warp] = d0;
        sh1[warp] = d1;
        shc[warp] = dc;
    }
    __syncthreads();

    if (warp == 0) {
        d0 = (lane < 8) ? sh0[lane] : 0.0;
        d1 = (lane < 8) ? sh1[lane] : 0.0;
        dc = (lane < 8) ? shc[lane] : 0LL;
#pragma unroll
        for (int o = 4; o > 0; o >>= 1) {
            d0 += __shfl_down_sync(0xFFFFFFFFu, d0, o);
            d1 += __shfl_down_sync(0xFFFFFFFFu, d1, o);
            dc += __shfl_down_sync(0xFFFFFFFFu, dc, o);
        }
        if (lane == 0) {
            atomicAdd(&g_db0, d0);
            atomicAdd(&g_db1, d1);
            atomicAdd((unsigned long long*)&g_ds, (unsigned long long)dc);
            __threadfence();
            unsigned int ticket = atomicAdd(&g_count, 1u);
            is_last = (ticket == gridDim.x - 1);
        }
    }
    __syncthreads();

    // ---- last block: tail, solve, write basis outputs, reset state
    if (is_last && threadIdx.x == 0) {
        double td0 = g_db0;
        double td1 = g_db1;
        long long tds = g_ds;

        int tail = n & 3;
        for (int k = n - tail; k < n; k++) {
            float a0 = 0.f, a1 = 0.f;
            int ac = 0;
            out[k] = lq_step(x[k], t, a0, a1, ac);
            td0 += (double)a0;
            td1 += (double)a1;
            tds += ac;
        }

        double N   = (double)n;
        double S   = (double)tds;
        double det = N * N - S * S;
        double v0  = (N * td0 - S * td1) / det;
        double v1  = (N * td1 - S * td0) / det;

        out[n]     = 0.9f * b0 + 0.1f * (float)v0;
        out[n + 1] = 0.9f * b1 + 0.1f * (float)v1;

        // Reset for next graph replay (deterministic: zero -> zero).
        g_db0 = 0.0;
        g_db1 = 0.0;
        g_ds  = 0;
        g_count = 0;
        __threadfence();
    }
}

extern "C" void kernel_launch(void* const* d_in, const int* in_sizes, int n_in,
                              void* d_out, int out_size) {
    int xi = 0, bi = 1;
    if (n_in >= 2 && in_sizes[0] == 2 && in_sizes[1] != 2) { xi = 1; bi = 0; }

    const float* x     = (const float*)d_in[xi];
    const float* basis = (const float*)d_in[bi];
    float* out         = (float*)d_out;

    int n = in_sizes[xi];

    const int threads = 256;
    const int blocks  = 1184;  // 8 per SM on 148-SM part, grid-stride
    lq_fused_kernel<<<blocks, threads>>>(x, basis, out, n);
}

// round 4
// speedup vs baseline: 1.4805x; 1.2125x over previous
#include <cuda_runtime.h>

// ---------------------------------------------------------------------------
// LQActiv (2-bit learned quantization), Q_T = 1 — single fused kernel.
//
// Algebraic form: level set is {±(B1±B0)}, B1=max|basis|, B0=min|basis|,
// midpoint thresholds {-B1, 0, +B1}. Per element:
//     q  = (|w| > B1) ? +1 : -1
//     wq = copysign(B1 + q*B0, w)
// Sufficient statistics (signs/order fixed up once in the final solve):
//     Sabs = Σ|w|      (-> Σ e_big*w   = σ_big  * Sabs)
//     Sqw  = Σ q*|w|   (-> Σ e_small*w = σ_small* Sqw)
//     Sq   = Σ q       (-> Σ e0*e1     = σ_bσ_s * Sq)
// ~8 instr/element. Last block (atomic ticket) does the scalar tail, the
// 2x2 solve, writes out[n..n+2), and re-zeros globals for graph replay.
// ---------------------------------------------------------------------------

__device__ double       g_dabs;
__device__ double       g_dqw;
__device__ double       g_dq;
__device__ unsigned int g_count;

__device__ __forceinline__ float lq_step(float w, float B0, float B1,
                                         float& sabs, float& sqw, float& sq) {
    float aw = fabsf(w);
    float qf = (aw > B1) ? 1.0f : -1.0f;
    float qv = copysignf(fmaf(qf, B0, B1), w);
    sabs += aw;                 // FADD with |.| modifier
    sqw   = fmaf(qf, aw, sqw);  // FFMA
    sq   += qf;                 // FADD (exact small ints in fp32)
    return qv;
}

__device__ __forceinline__ float4 lq_step4(float4 v, float B0, float B1,
                                           float& sabs, float& sqw, float& sq) {
    float4 o;
    o.x = lq_step(v.x, B0, B1, sabs, sqw, sq);
    o.y = lq_step(v.y, B0, B1, sabs, sqw, sq);
    o.z = lq_step(v.z, B0, B1, sabs, sqw, sq);
    o.w = lq_step(v.w, B0, B1, sabs, sqw, sq);
    return o;
}

__global__ void __launch_bounds__(256)
lq_fused_kernel(const float* __restrict__ x,
                const float* __restrict__ basis,
                float* __restrict__ out, int n) {
    const float b0 = __ldg(&basis[0]);
    const float b1 = __ldg(&basis[1]);
    const float a0 = fabsf(b0), a1 = fabsf(b1);
    const float B1 = fmaxf(a0, a1);
    const float B0 = fminf(a0, a1);

    const float4* __restrict__ x4   = (const float4*)x;
    float4* __restrict__       out4 = (float4*)out;
    const int n4 = n >> 2;

    float sabs = 0.f, sqw = 0.f, sq = 0.f;

    const int stride = gridDim.x * blockDim.x;
    int i = blockIdx.x * blockDim.x + threadIdx.x;

    // 4-deep batched grid-stride loop: 4 loads in flight, then compute+store.
    for (; i + 3 * stride < n4; i += 4 * stride) {
        float4 v0 = __ldcs(&x4[i]);
        float4 v1 = __ldcs(&x4[i + stride]);
        float4 v2 = __ldcs(&x4[i + 2 * stride]);
        float4 v3 = __ldcs(&x4[i + 3 * stride]);
        float4 q0 = lq_step4(v0, B0, B1, sabs, sqw, sq);
        float4 q1 = lq_step4(v1, B0, B1, sabs, sqw, sq);
        float4 q2 = lq_step4(v2, B0, B1, sabs, sqw, sq);
        float4 q3 = lq_step4(v3, B0, B1, sabs, sqw, sq);
        __stcs(&out4[i], q0);
        __stcs(&out4[i + stride], q1);
        __stcs(&out4[i + 2 * stride], q2);
        __stcs(&out4[i + 3 * stride], q3);
    }
    for (; i < n4; i += stride) {
        float4 v = __ldcs(&x4[i]);
        float4 q = lq_step4(v, B0, B1, sabs, sqw, sq);
        __stcs(&out4[i], q);
    }

    // ---- reductions: warp shuffle (fp64), shared, global atomics
    double d0 = (double)sabs;
    double d1 = (double)sqw;
    double d2 = (double)sq;

#pragma unroll
    for (int o = 16; o > 0; o >>= 1) {
        d0 += __shfl_down_sync(0xFFFFFFFFu, d0, o);
        d1 += __shfl_down_sync(0xFFFFFFFFu, d1, o);
        d2 += __shfl_down_sync(0xFFFFFFFFu, d2, o);
    }

    __shared__ double sh0[8], sh1[8], sh2[8];
    __shared__ bool   is_last;

    int lane = threadIdx.x & 31;
    int warp = threadIdx.x >> 5;
    if (lane == 0) { sh0[warp] = d0; sh1[warp] = d1; sh2[warp] = d2; }
    __syncthreads();

    if (warp == 0) {
        d0 = (lane < 8) ? sh0[lane] : 0.0;
        d1 = (lane < 8) ? sh1[lane] : 0.0;
        d2 = (lane < 8) ? sh2[lane] : 0.0;
#pragma unroll
        for (int o = 4; o > 0; o >>= 1) {
            d0 += __shfl_down_sync(0xFFFFFFFFu, d0, o);
            d1 += __shfl_down_sync(0xFFFFFFFFu, d1, o);
            d2 += __shfl_down_sync(0xFFFFFFFFu, d2, o);
        }
        if (lane == 0) {
            atomicAdd(&g_dabs, d0);
            atomicAdd(&g_dqw, d1);
            atomicAdd(&g_dq, d2);
            __threadfence();
            unsigned int ticket = atomicAdd(&g_count, 1u);
            is_last = (ticket == gridDim.x - 1);
        }
    }
    __syncthreads();

    // ---- last block: tail, 2x2 solve, write basis outputs, reset state
    if (is_last && threadIdx.x == 0) {
        double tabs = g_dabs;
        double tqw  = g_dqw;
        double tq   = g_dq;

        int tail = n & 3;
        for (int k = n - tail; k < n; k++) {
            float p0 = 0.f, p1 = 0.f, p2 = 0.f;
            out[k] = lq_step(x[k], B0, B1, p0, p1, p2);
            tabs += (double)p0;
            tqw  += (double)p1;
            tq   += (double)p2;
        }

        // Map (big/small, magnitudes) statistics back to basis index order.
        int big = (a1 >= a0) ? 1 : 0;
        float bbig   = big ? b1 : b0;
        float bsmall = big ? b0 : b1;
        double sgb = (bbig   >= 0.f) ? 1.0 : -1.0;
        double sgs = (bsmall >= 0.f) ? 1.0 : -1.0;

        double bB = sgb * tabs;        // Σ e_big   * w
        double bS = sgs * tqw;         // Σ e_small * w
        double S  = sgb * sgs * tq;    // Σ e0 * e1
        double N  = (double)n;

        double det    = N * N - S * S;
        double vbig   = (N * bB - S * bS) / det;
        double vsmall = (N * bS - S * bB) / det;

        double v0 = big ? vsmall : vbig;
        double v1 = big ? vbig : vsmall;

        out[n]     = 0.9f * b0 + 0.1f * (float)v0;
        out[n + 1] = 0.9f * b1 + 0.1f * (float)v1;

        // Reset for next graph replay (deterministic: zero -> zero).
        g_dabs = 0.0;
        g_dqw  = 0.0;
        g_dq   = 0.0;
        g_count = 0;
        __threadfence();
    }
}

extern "C" void kernel_launch(void* const* d_in, const int* in_sizes, int n_in,
                              void* d_out, int out_size) {
    int xi = 0, bi = 1;
    if (n_in >= 2 && in_sizes[0] == 2 && in_sizes[1] != 2) { xi = 1; bi = 0; }

    const float* x     = (const float*)d_in[xi];
    const float* basis = (const float*)d_in[bi];
    float* out         = (float*)d_out;

    int n = in_sizes[xi];

    const int threads = 256;
    const int blocks  = 1184;  // 8 per SM, grid-stride
    lq_fused_kernel<<<blocks, threads>>>(x, basis, out, n);
}